// round 15
// baseline (speedup 1.0000x reference)
#include <cuda_runtime.h>
#include <math.h>

#define C_   16
#define I_   64
#define H_   40
#define T_   512
#define G_   120
#define GP   128

typedef unsigned long long u64;

// 1 GB scratch: gi[b][c][t][g], rows of 120 floats (b_ih folded in)
__device__ float g_gi[(size_t)256 * 16 * 512 * 120];

__device__ __forceinline__ u64 pack2(float lo, float hi) {
    u64 r;
    asm("mov.b64 %0, {%1, %2};"
        : "=l"(r) : "r"(__float_as_uint(lo)), "r"(__float_as_uint(hi)));
    return r;
}
__device__ __forceinline__ u64 dup2(float v) {
    u64 r;
    asm("mov.b64 %0, {%1, %1};" : "=l"(r) : "r"(__float_as_uint(v)));
    return r;
}
__device__ __forceinline__ u64 fma2(u64 a, u64 b, u64 c) {
    u64 d;
    asm("fma.rn.f32x2 %0, %1, %2, %3;" : "=l"(d) : "l"(a), "l"(b), "l"(c));
    return d;
}
__device__ __forceinline__ float tanh_ap(float x) {
    float r;
    asm("tanh.approx.f32 %0, %1;" : "=f"(r) : "f"(x));
    return r;
}
__device__ __forceinline__ float sig_ap(float v) {
    return fmaf(0.5f, tanh_ap(0.5f * v), 0.5f);
}
__device__ __forceinline__ float sigf(float v) {
    return __fdividef(1.0f, 1.0f + __expf(-v));
}

// ============================================================================
// Kernel 1: gi = W_ih . x + b_ih. Persistent grid 296, 256 thr, 2 CTAs/SM.
// (R11/R13 version, measured ~843us)
// ============================================================================
#define K1_GRID 296
#define K1_NIT  4096                 // 16 c x 16 bblk x 16 tq
#define K1_BN   16
#define K1_TCH  8
#define K1_WIH  0                    // [64][128]
#define K1_X    (K1_WIH + I_ * GP)   // [8][64][16]
#define K1_TOT  (K1_X + K1_TCH * I_ * K1_BN)   // 16384 floats = 65536 B

__global__ void __launch_bounds__(256, 2)
gi_gemm_kernel(const float* __restrict__ x,
               const float* __restrict__ Wih,
               const float* __restrict__ bih)
{
    extern __shared__ float sm[];
    const int tid = threadIdx.x;
    const int bid = blockIdx.x;

    const int start = (K1_NIT * bid) / K1_GRID;
    const int end   = (K1_NIT * (bid + 1)) / K1_GRID;

    const int wid = tid >> 5;
    const int gt  = tid & 31;
    const int th  = tid & 1;
    const int lb  = (tid >> 1) & 15;
    const int lig = tid >> 5;

    const float* wI = sm + K1_WIH + 2 * gt;

    int c_cur = -1;
    u64 bI0 = 0ull, bI1 = 0ull;

    for (int it = start; it < end; ++it) {
        const int c  = it >> 8;
        const int rm = it & 255;
        const int b0 = (rm >> 4) * K1_BN;
        const int t0 = (rm & 15) * 32;

        if (c != c_cur) {
            __syncthreads();
            for (int p = tid; p < I_ * GP; p += 256) {
                int k = p >> 7, g = p & 127;
                sm[K1_WIH + p] = (g < G_) ? Wih[(c * G_ + g) * I_ + k] : 0.0f;
            }
            const int g0 = 2 * gt, g1 = 64 + 2 * gt;
            float bi1a = (g1     < G_) ? bih[c * G_ + g1]     : 0.0f;
            float bi1b = (g1 + 1 < G_) ? bih[c * G_ + g1 + 1] : 0.0f;
            bI0 = pack2(bih[c * G_ + g0], bih[c * G_ + g0 + 1]);
            bI1 = pack2(bi1a, bi1b);
            c_cur = c;
            __syncthreads();
        }

        const float* xg = x + ((size_t)(b0 + lb) * C_ + c) * (size_t)(I_ * T_);

        for (int tc = t0; tc < t0 + 32; tc += K1_TCH) {
            __syncthreads();
            #pragma unroll
            for (int r = 0; r < 8; ++r) {
                int i = lig + (r << 3);
                float4 v = *(const float4*)(xg + i * T_ + tc + 4 * th);
                float* xp = sm + K1_X + i * 16 + lb;    // tt stride = 1024
                xp[(4 * th + 0) * 1024] = v.x;
                xp[(4 * th + 1) * 1024] = v.y;
                xp[(4 * th + 2) * 1024] = v.z;
                xp[(4 * th + 3) * 1024] = v.w;
            }
            __syncthreads();

            u64 a0[16], a1[16];
            #pragma unroll
            for (int b = 0; b < 16; ++b) { a0[b] = bI0; a1[b] = bI1; }
            const float* xr = sm + K1_X + wid * 1024;
            #pragma unroll 2
            for (int k = 0; k < I_; ++k) {
                u64 w0 = *(const u64*)(wI + k * GP);
                u64 w1 = *(const u64*)(wI + k * GP + 64);
                const float* xk = xr + k * 16;
                float4 xa = *(const float4*)(xk);
                float4 xb = *(const float4*)(xk + 4);
                float4 xc = *(const float4*)(xk + 8);
                float4 xd = *(const float4*)(xk + 12);
                u64 d0 = dup2(xa.x), d1 = dup2(xa.y), d2 = dup2(xa.z), d3 = dup2(xa.w);
                u64 d4 = dup2(xb.x), d5 = dup2(xb.y), d6 = dup2(xb.z), d7 = dup2(xb.w);
                u64 d8 = dup2(xc.x), d9 = dup2(xc.y), da = dup2(xc.z), db = dup2(xc.w);
                u64 dc = dup2(xd.x), dd = dup2(xd.y), de = dup2(xd.z), df = dup2(xd.w);
                a0[0]  = fma2(w0, d0, a0[0]);  a1[0]  = fma2(w1, d0, a1[0]);
                a0[1]  = fma2(w0, d1, a0[1]);  a1[1]  = fma2(w1, d1, a1[1]);
                a0[2]  = fma2(w0, d2, a0[2]);  a1[2]  = fma2(w1, d2, a1[2]);
                a0[3]  = fma2(w0, d3, a0[3]);  a1[3]  = fma2(w1, d3, a1[3]);
                a0[4]  = fma2(w0, d4, a0[4]);  a1[4]  = fma2(w1, d4, a1[4]);
                a0[5]  = fma2(w0, d5, a0[5]);  a1[5]  = fma2(w1, d5, a1[5]);
                a0[6]  = fma2(w0, d6, a0[6]);  a1[6]  = fma2(w1, d6, a1[6]);
                a0[7]  = fma2(w0, d7, a0[7]);  a1[7]  = fma2(w1, d7, a1[7]);
                a0[8]  = fma2(w0, d8, a0[8]);  a1[8]  = fma2(w1, d8, a1[8]);
                a0[9]  = fma2(w0, d9, a0[9]);  a1[9]  = fma2(w1, d9, a1[9]);
                a0[10] = fma2(w0, da, a0[10]); a1[10] = fma2(w1, da, a1[10]);
                a0[11] = fma2(w0, db, a0[11]); a1[11] = fma2(w1, db, a1[11]);
                a0[12] = fma2(w0, dc, a0[12]); a1[12] = fma2(w1, dc, a1[12]);
                a0[13] = fma2(w0, dd, a0[13]); a1[13] = fma2(w1, dd, a1[13]);
                a0[14] = fma2(w0, de, a0[14]); a1[14] = fma2(w1, de, a1[14]);
                a0[15] = fma2(w0, df, a0[15]); a1[15] = fma2(w1, df, a1[15]);
            }
            const int t = tc + wid;
            #pragma unroll
            for (int b = 0; b < 16; ++b) {
                float* gp = g_gi + (((size_t)(b0 + b) * C_ + c) * T_ + t) * G_;
                *(u64*)(gp + 2 * gt) = a0[b];
                if (gt < 28) *(u64*)(gp + 64 + 2 * gt) = a1[b];
            }
        }
    }
}

// ============================================================================
// Kernel 2: recurrence, k-split warp pairs + DUPLICATED h (u64) + tanh.approx.
// 256 thr, 2 CTAs/SM, grid 256.
// ============================================================================
#define K2_BN 16
#define PRS2  136
#define KH    20
#define HD    20    // h row stride in u64 (2-way max STS conflict)
#define K2_WST 0                               // [40][128] floats = 5120
#define K2_HD  (K2_WST + H_ * GP)              // u64 [40][20] = 1600 floats
#define K2_GH  (K2_HD + H_ * HD * 2)           // [2][16][136] = 4352
#define K2_GIB (K2_GH + 2 * K2_BN * PRS2)      // [4 pairs][2 buf][4 b][120] = 3840
#define K2_TOT (K2_GIB + 4 * 2 * 4 * G_)       // 14912 floats = 59648 B

__device__ __forceinline__ void cp16(unsigned smem_addr, const void* gptr) {
    asm volatile("cp.async.ca.shared.global [%0], [%1], 16;"
                 :: "r"(smem_addr), "l"(gptr));
}

__global__ void __launch_bounds__(256, 2)
gru_rec_kernel(const float* __restrict__ Whh,
               const float* __restrict__ bhh,
               const float* __restrict__ Wfc,
               const float* __restrict__ bfc,
               float* __restrict__ out)
{
    extern __shared__ float sm[];
    u64* hd = (u64*)(sm + K2_HD);
    const int tid = threadIdx.x;
    const int c   = blockIdx.x & 15;
    const int b0  = (blockIdx.x >> 4) * K2_BN;

    for (int p = tid; p < H_ * GP; p += 256) {
        int k = p >> 7, g = p & 127;
        sm[K2_WST + p] = (g < G_) ? Whh[(c * G_ + g) * H_ + k] : 0.0f;
    }
    for (int p = tid; p < H_ * HD; p += 256) hd[p] = 0ull;
    __syncthreads();

    const int wid  = tid >> 5;
    const int gt   = tid & 31;
    const int pair = wid >> 1;
    const int half = wid & 1;
    const int bq   = pair * 4;
    const int barid = 1 + pair;

    u64 w0r[KH], w1r[KH];
    #pragma unroll
    for (int kk = 0; kk < KH; ++kk) {
        int k = half * KH + kk;
        w0r[kk] = *(const u64*)(sm + K2_WST + k * GP + 2 * gt);
        w1r[kk] = *(const u64*)(sm + K2_WST + k * GP + 64 + 2 * gt);
    }

    const int g0 = 2 * gt, g1 = 64 + 2 * gt;
    u64 bH0 = 0ull, bH1 = 0ull;
    if (half == 0) {
        float b1a = (g1     < G_) ? bhh[c * G_ + g1]     : 0.0f;
        float b1b = (g1 + 1 < G_) ? bhh[c * G_ + g1 + 1] : 0.0f;
        bH0 = pack2(bhh[c * G_ + g0], bhh[c * G_ + g0 + 1]);
        bH1 = pack2(b1a, b1b);
    }

    const int mb = bq + 2 * half;
    const unsigned gib_pair =
        (unsigned)__cvta_generic_to_shared(sm + K2_GIB + pair * 960);
    const int ch0 = gt,      b_of0 = ch0 / 30, o_of0 = ch0 % 30;
    const int ch1 = gt + 32, b_of1 = ch1 / 30, o_of1 = ch1 % 30;
    const size_t r0 = ((size_t)(b0 + mb + b_of0) * C_ + c) * T_;
    const size_t r1 = ((size_t)(b0 + mb + b_of1) * C_ + c) * T_;
    const unsigned d0off = (unsigned)((2 * half + b_of0) * G_ + o_of0 * 4) * 4u;
    const unsigned d1off = (unsigned)((2 * half + b_of1) * G_ + o_of1 * 4) * 4u;

    cp16(gib_pair + d0off, g_gi + r0 * G_ + (size_t)o_of0 * 4);
    if (ch1 < 60)
        cp16(gib_pair + d1off, g_gi + r1 * G_ + (size_t)o_of1 * 4);
    asm volatile("cp.async.commit_group;");

    const int lp  = half * 32 + gt;
    const int cb  = lp & 3;
    const int hh0 = lp >> 2;

    const float* ghA = sm + K2_GH + (bq + cb) * PRS2;
    const float* ghB = ghA + K2_BN * PRS2;
    float* myGH = sm + K2_GH + half * (K2_BN * PRS2);

    for (int t = 0; t < T_; ++t) {
        if (t + 1 < T_) {
            unsigned dst = gib_pair + (unsigned)(((t + 1) & 1) * 480) * 4u;
            cp16(dst + d0off, g_gi + (r0 + t + 1) * G_ + (size_t)o_of0 * 4);
            if (ch1 < 60)
                cp16(dst + d1off, g_gi + (r1 + t + 1) * G_ + (size_t)o_of1 * 4);
        }
        asm volatile("cp.async.commit_group;");
        asm volatile("cp.async.wait_group 1;");

        // ---- partial hidden projection: duplicated h, no dup2 in loop ----
        u64 a0[4], a1[4];
        a0[0] = bH0; a0[1] = bH0; a0[2] = bH0; a0[3] = bH0;
        a1[0] = bH1; a1[1] = bH1; a1[2] = bH1; a1[3] = bH1;
        const u64* hrow = hd + half * KH * HD + bq;
        #pragma unroll
        for (int kk = 0; kk < KH; ++kk) {
            ulonglong2 hA = *(const ulonglong2*)(hrow + kk * HD);
            ulonglong2 hB = *(const ulonglong2*)(hrow + kk * HD + 2);
            a0[0] = fma2(w0r[kk], hA.x, a0[0]); a1[0] = fma2(w1r[kk], hA.x, a1[0]);
            a0[1] = fma2(w0r[kk], hA.y, a0[1]); a1[1] = fma2(w1r[kk], hA.y, a1[1]);
            a0[2] = fma2(w0r[kk], hB.x, a0[2]); a1[2] = fma2(w1r[kk], hB.x, a1[2]);
            a0[3] = fma2(w0r[kk], hB.y, a0[3]); a1[3] = fma2(w1r[kk], hB.y, a1[3]);
        }
        #pragma unroll
        for (int b = 0; b < 4; ++b) {
            float* pg = myGH + (bq + b) * PRS2 + 2 * gt;
            *(u64*)pg        = a0[b];
            *(u64*)(pg + 64) = a1[b];
        }
        asm volatile("bar.sync %0, 64;" :: "r"(barid) : "memory");

        // ---- combine (tanh.approx gates) + duplicated-h update ----
        {
            const float* gi = sm + K2_GIB + pair * 960 + (t & 1) * 480 + cb * G_;
            #pragma unroll
            for (int q = 0; q < 2; ++q) {
                int hh = hh0 + 16 * q;
                float rg = sig_ap(gi[hh]      + ghA[hh]      + ghB[hh]);
                float zg = sig_ap(gi[40 + hh] + ghA[40 + hh] + ghB[40 + hh]);
                float hn = ghA[80 + hh] + ghB[80 + hh];
                float ng = tanh_ap(fmaf(rg, hn, gi[80 + hh]));
                u64* hp = hd + hh * HD + bq + cb;
                float ho = *(const float*)hp;
                hd[hh * HD + bq + cb] = dup2(fmaf(zg, ho - ng, ng));
            }
            if (lp < 32) {
                int hh = hh0 + 32;
                float rg = sig_ap(gi[hh]      + ghA[hh]      + ghB[hh]);
                float zg = sig_ap(gi[40 + hh] + ghA[40 + hh] + ghB[40 + hh]);
                float hn = ghA[80 + hh] + ghB[80 + hh];
                float ng = tanh_ap(fmaf(rg, hn, gi[80 + hh]));
                u64* hp = hd + hh * HD + bq + cb;
                float ho = *(const float*)hp;
                hd[hh * HD + bq + cb] = dup2(fmaf(zg, ho - ng, ng));
            }
        }
        asm volatile("bar.sync %0, 64;" :: "r"(barid) : "memory");
    }

    __syncthreads();
    if (tid < K2_BN) {
        float acc = bfc[c];
        #pragma unroll
        for (int h2 = 0; h2 < H_; ++h2)
            acc += *(const float*)(hd + h2 * HD + tid) * Wfc[c * H_ + h2];
        out[(size_t)(b0 + tid) * C_ + c] = sigf(acc);
    }
}

extern "C" void kernel_launch(void* const* d_in, const int* in_sizes, int n_in,
                              void* d_out, int out_size)
{
    const float* x   = (const float*)d_in[0];
    const float* Wih = (const float*)d_in[1];
    const float* Whh = (const float*)d_in[2];
    const float* bih = (const float*)d_in[3];
    const float* bhh = (const float*)d_in[4];
    const float* Wfc = (const float*)d_in[5];
    const float* bfc = (const float*)d_in[6];
    float* out = (float*)d_out;

    const int sm1 = K1_TOT * (int)sizeof(float);   // 65536
    const int sm2 = K2_TOT * (int)sizeof(float);   // 59648
    cudaFuncSetAttribute(gi_gemm_kernel,
                         cudaFuncAttributeMaxDynamicSharedMemorySize, sm1);
    cudaFuncSetAttribute(gru_rec_kernel,
                         cudaFuncAttributeMaxDynamicSharedMemorySize, sm2);

    gi_gemm_kernel<<<K1_GRID, 256, sm1>>>(x, Wih, bih);
    gru_rec_kernel<<<256, 256, sm2>>>(Whh, bhh, Wfc, bfc, out);
}

// round 16
// speedup vs baseline: 1.0580x; 1.0580x over previous
#include <cuda_runtime.h>
#include <math.h>

#define C_   16
#define I_   64
#define H_   40
#define T_   512
#define G_   120
#define GP   128

typedef unsigned long long u64;

// 1 GB scratch: gi[b][c][t][g], rows of 120 floats (b_ih folded in)
__device__ float g_gi[(size_t)256 * 16 * 512 * 120];

__device__ __forceinline__ u64 pack2(float lo, float hi) {
    u64 r;
    asm("mov.b64 %0, {%1, %2};"
        : "=l"(r) : "r"(__float_as_uint(lo)), "r"(__float_as_uint(hi)));
    return r;
}
__device__ __forceinline__ u64 dup2(float v) {
    u64 r;
    asm("mov.b64 %0, {%1, %1};" : "=l"(r) : "r"(__float_as_uint(v)));
    return r;
}
__device__ __forceinline__ u64 fma2(u64 a, u64 b, u64 c) {
    u64 d;
    asm("fma.rn.f32x2 %0, %1, %2, %3;" : "=l"(d) : "l"(a), "l"(b), "l"(c));
    return d;
}
__device__ __forceinline__ float tanh_ap(float x) {
    float r;
    asm("tanh.approx.f32 %0, %1;" : "=f"(r) : "f"(x));
    return r;
}
__device__ __forceinline__ float sig_ap(float v) {
    return fmaf(0.5f, tanh_ap(0.5f * v), 0.5f);
}
__device__ __forceinline__ float sigf(float v) {
    return __fdividef(1.0f, 1.0f + __expf(-v));
}

// ============================================================================
// Kernel 1: gi = W_ih . x + b_ih. Persistent grid 296, 256 thr, 2 CTAs/SM.
// (stable ~840us version)
// ============================================================================
#define K1_GRID 296
#define K1_NIT  4096                 // 16 c x 16 bblk x 16 tq
#define K1_BN   16
#define K1_TCH  8
#define K1_WIH  0                    // [64][128]
#define K1_X    (K1_WIH + I_ * GP)   // [8][64][16]
#define K1_TOT  (K1_X + K1_TCH * I_ * K1_BN)   // 16384 floats = 65536 B

__global__ void __launch_bounds__(256, 2)
gi_gemm_kernel(const float* __restrict__ x,
               const float* __restrict__ Wih,
               const float* __restrict__ bih)
{
    extern __shared__ float sm[];
    const int tid = threadIdx.x;
    const int bid = blockIdx.x;

    const int start = (K1_NIT * bid) / K1_GRID;
    const int end   = (K1_NIT * (bid + 1)) / K1_GRID;

    const int wid = tid >> 5;
    const int gt  = tid & 31;
    const int th  = tid & 1;
    const int lb  = (tid >> 1) & 15;
    const int lig = tid >> 5;

    const float* wI = sm + K1_WIH + 2 * gt;

    int c_cur = -1;
    u64 bI0 = 0ull, bI1 = 0ull;

    for (int it = start; it < end; ++it) {
        const int c  = it >> 8;
        const int rm = it & 255;
        const int b0 = (rm >> 4) * K1_BN;
        const int t0 = (rm & 15) * 32;

        if (c != c_cur) {
            __syncthreads();
            for (int p = tid; p < I_ * GP; p += 256) {
                int k = p >> 7, g = p & 127;
                sm[K1_WIH + p] = (g < G_) ? Wih[(c * G_ + g) * I_ + k] : 0.0f;
            }
            const int g0 = 2 * gt, g1 = 64 + 2 * gt;
            float bi1a = (g1     < G_) ? bih[c * G_ + g1]     : 0.0f;
            float bi1b = (g1 + 1 < G_) ? bih[c * G_ + g1 + 1] : 0.0f;
            bI0 = pack2(bih[c * G_ + g0], bih[c * G_ + g0 + 1]);
            bI1 = pack2(bi1a, bi1b);
            c_cur = c;
            __syncthreads();
        }

        const float* xg = x + ((size_t)(b0 + lb) * C_ + c) * (size_t)(I_ * T_);

        for (int tc = t0; tc < t0 + 32; tc += K1_TCH) {
            __syncthreads();
            #pragma unroll
            for (int r = 0; r < 8; ++r) {
                int i = lig + (r << 3);
                float4 v = *(const float4*)(xg + i * T_ + tc + 4 * th);
                float* xp = sm + K1_X + i * 16 + lb;    // tt stride = 1024
                xp[(4 * th + 0) * 1024] = v.x;
                xp[(4 * th + 1) * 1024] = v.y;
                xp[(4 * th + 2) * 1024] = v.z;
                xp[(4 * th + 3) * 1024] = v.w;
            }
            __syncthreads();

            u64 a0[16], a1[16];
            #pragma unroll
            for (int b = 0; b < 16; ++b) { a0[b] = bI0; a1[b] = bI1; }
            const float* xr = sm + K1_X + wid * 1024;
            #pragma unroll 2
            for (int k = 0; k < I_; ++k) {
                u64 w0 = *(const u64*)(wI + k * GP);
                u64 w1 = *(const u64*)(wI + k * GP + 64);
                const float* xk = xr + k * 16;
                float4 xa = *(const float4*)(xk);
                float4 xb = *(const float4*)(xk + 4);
                float4 xc = *(const float4*)(xk + 8);
                float4 xd = *(const float4*)(xk + 12);
                u64 d0 = dup2(xa.x), d1 = dup2(xa.y), d2 = dup2(xa.z), d3 = dup2(xa.w);
                u64 d4 = dup2(xb.x), d5 = dup2(xb.y), d6 = dup2(xb.z), d7 = dup2(xb.w);
                u64 d8 = dup2(xc.x), d9 = dup2(xc.y), da = dup2(xc.z), db = dup2(xc.w);
                u64 dc = dup2(xd.x), dd = dup2(xd.y), de = dup2(xd.z), df = dup2(xd.w);
                a0[0]  = fma2(w0, d0, a0[0]);  a1[0]  = fma2(w1, d0, a1[0]);
                a0[1]  = fma2(w0, d1, a0[1]);  a1[1]  = fma2(w1, d1, a1[1]);
                a0[2]  = fma2(w0, d2, a0[2]);  a1[2]  = fma2(w1, d2, a1[2]);
                a0[3]  = fma2(w0, d3, a0[3]);  a1[3]  = fma2(w1, d3, a1[3]);
                a0[4]  = fma2(w0, d4, a0[4]);  a1[4]  = fma2(w1, d4, a1[4]);
                a0[5]  = fma2(w0, d5, a0[5]);  a1[5]  = fma2(w1, d5, a1[5]);
                a0[6]  = fma2(w0, d6, a0[6]);  a1[6]  = fma2(w1, d6, a1[6]);
                a0[7]  = fma2(w0, d7, a0[7]);  a1[7]  = fma2(w1, d7, a1[7]);
                a0[8]  = fma2(w0, d8, a0[8]);  a1[8]  = fma2(w1, d8, a1[8]);
                a0[9]  = fma2(w0, d9, a0[9]);  a1[9]  = fma2(w1, d9, a1[9]);
                a0[10] = fma2(w0, da, a0[10]); a1[10] = fma2(w1, da, a1[10]);
                a0[11] = fma2(w0, db, a0[11]); a1[11] = fma2(w1, db, a1[11]);
                a0[12] = fma2(w0, dc, a0[12]); a1[12] = fma2(w1, dc, a1[12]);
                a0[13] = fma2(w0, dd, a0[13]); a1[13] = fma2(w1, dd, a1[13]);
                a0[14] = fma2(w0, de, a0[14]); a1[14] = fma2(w1, de, a1[14]);
                a0[15] = fma2(w0, df, a0[15]); a1[15] = fma2(w1, df, a1[15]);
            }
            const int t = tc + wid;
            #pragma unroll
            for (int b = 0; b < 16; ++b) {
                float* gp = g_gi + (((size_t)(b0 + b) * C_ + c) * T_ + t) * G_;
                *(u64*)(gp + 2 * gt) = a0[b];
                if (gt < 28) *(u64*)(gp + 64 + 2 * gt) = a1[b];
            }
        }
    }
}

// ============================================================================
// Kernel 2: recurrence, k-split warp pairs (stable 708us shape) +
// tanh.approx gates in combine.
// ============================================================================
#define K2_BN 16
#define HS2   20
#define PRS2  136
#define KH    20
#define K2_WST 0
#define K2_H   (K2_WST + H_ * GP)
#define K2_GH  (K2_H + H_ * HS2)
#define K2_GIB (K2_GH + 2 * K2_BN * PRS2)
#define K2_TOT (K2_GIB + 4 * 2 * 4 * G_)

__device__ __forceinline__ void cp16(unsigned smem_addr, const void* gptr) {
    asm volatile("cp.async.ca.shared.global [%0], [%1], 16;"
                 :: "r"(smem_addr), "l"(gptr));
}

__global__ void __launch_bounds__(256, 2)
gru_rec_kernel(const float* __restrict__ Whh,
               const float* __restrict__ bhh,
               const float* __restrict__ Wfc,
               const float* __restrict__ bfc,
               float* __restrict__ out)
{
    extern __shared__ float sm[];
    const int tid = threadIdx.x;
    const int c   = blockIdx.x & 15;
    const int b0  = (blockIdx.x >> 4) * K2_BN;

    for (int p = tid; p < H_ * GP; p += 256) {
        int k = p >> 7, g = p & 127;
        sm[K2_WST + p] = (g < G_) ? Whh[(c * G_ + g) * H_ + k] : 0.0f;
    }
    for (int p = tid; p < H_ * HS2; p += 256) sm[K2_H + p] = 0.0f;
    __syncthreads();

    const int wid  = tid >> 5;
    const int gt   = tid & 31;
    const int pair = wid >> 1;
    const int half = wid & 1;
    const int bq   = pair * 4;
    const int barid = 1 + pair;

    u64 w0r[KH], w1r[KH];
    #pragma unroll
    for (int kk = 0; kk < KH; ++kk) {
        int k = half * KH + kk;
        w0r[kk] = *(const u64*)(sm + K2_WST + k * GP + 2 * gt);
        w1r[kk] = *(const u64*)(sm + K2_WST + k * GP + 64 + 2 * gt);
    }

    const int g0 = 2 * gt, g1 = 64 + 2 * gt;
    u64 bH0 = 0ull, bH1 = 0ull;
    if (half == 0) {
        float b1a = (g1     < G_) ? bhh[c * G_ + g1]     : 0.0f;
        float b1b = (g1 + 1 < G_) ? bhh[c * G_ + g1 + 1] : 0.0f;
        bH0 = pack2(bhh[c * G_ + g0], bhh[c * G_ + g0 + 1]);
        bH1 = pack2(b1a, b1b);
    }

    const int mb = bq + 2 * half;
    const unsigned gib_pair =
        (unsigned)__cvta_generic_to_shared(sm + K2_GIB + pair * 960);
    const int ch0 = gt,      b_of0 = ch0 / 30, o_of0 = ch0 % 30;
    const int ch1 = gt + 32, b_of1 = ch1 / 30, o_of1 = ch1 % 30;
    const size_t r0 = ((size_t)(b0 + mb + b_of0) * C_ + c) * T_;
    const size_t r1 = ((size_t)(b0 + mb + b_of1) * C_ + c) * T_;
    const unsigned d0off = (unsigned)((2 * half + b_of0) * G_ + o_of0 * 4) * 4u;
    const unsigned d1off = (unsigned)((2 * half + b_of1) * G_ + o_of1 * 4) * 4u;

    cp16(gib_pair + d0off, g_gi + r0 * G_ + (size_t)o_of0 * 4);
    if (ch1 < 60)
        cp16(gib_pair + d1off, g_gi + r1 * G_ + (size_t)o_of1 * 4);
    asm volatile("cp.async.commit_group;");

    const int lp  = half * 32 + gt;
    const int cb  = lp & 3;
    const int hh0 = lp >> 2;

    const float* ghA = sm + K2_GH + (bq + cb) * PRS2;
    const float* ghB = ghA + K2_BN * PRS2;
    float* myGH = sm + K2_GH + half * (K2_BN * PRS2);

    for (int t = 0; t < T_; ++t) {
        if (t + 1 < T_) {
            unsigned dst = gib_pair + (unsigned)(((t + 1) & 1) * 480) * 4u;
            cp16(dst + d0off, g_gi + (r0 + t + 1) * G_ + (size_t)o_of0 * 4);
            if (ch1 < 60)
                cp16(dst + d1off, g_gi + (r1 + t + 1) * G_ + (size_t)o_of1 * 4);
        }
        asm volatile("cp.async.commit_group;");
        asm volatile("cp.async.wait_group 1;");

        u64 a0[4], a1[4];
        a0[0] = bH0; a0[1] = bH0; a0[2] = bH0; a0[3] = bH0;
        a1[0] = bH1; a1[1] = bH1; a1[2] = bH1; a1[3] = bH1;
        const float* hrow = sm + K2_H + half * KH * HS2 + bq;
        #pragma unroll
        for (int kk = 0; kk < KH; ++kk) {
            float4 hv = *(const float4*)(hrow + kk * HS2);
            u64 d0 = dup2(hv.x), d1 = dup2(hv.y), d2 = dup2(hv.z), d3 = dup2(hv.w);
            a0[0] = fma2(w0r[kk], d0, a0[0]); a1[0] = fma2(w1r[kk], d0, a1[0]);
            a0[1] = fma2(w0r[kk], d1, a0[1]); a1[1] = fma2(w1r[kk], d1, a1[1]);
            a0[2] = fma2(w0r[kk], d2, a0[2]); a1[2] = fma2(w1r[kk], d2, a1[2]);
            a0[3] = fma2(w0r[kk], d3, a0[3]); a1[3] = fma2(w1r[kk], d3, a1[3]);
        }
        #pragma unroll
        for (int b = 0; b < 4; ++b) {
            float* pg = myGH + (bq + b) * PRS2 + 2 * gt;
            *(u64*)pg        = a0[b];
            *(u64*)(pg + 64) = a1[b];
        }
        asm volatile("bar.sync %0, 64;" :: "r"(barid) : "memory");

        {
            const float* gi = sm + K2_GIB + pair * 960 + (t & 1) * 480 + cb * G_;
            #pragma unroll
            for (int q = 0; q < 2; ++q) {
                int hh = hh0 + 16 * q;
                float rg = sig_ap(gi[hh]      + ghA[hh]      + ghB[hh]);
                float zg = sig_ap(gi[40 + hh] + ghA[40 + hh] + ghB[40 + hh]);
                float hn = ghA[80 + hh] + ghB[80 + hh];
                float ng = tanh_ap(fmaf(rg, hn, gi[80 + hh]));
                float* hp = sm + K2_H + hh * HS2 + bq + cb;
                float ho = *hp;
                *hp = fmaf(zg, ho - ng, ng);
            }
            if (lp < 32) {
                int hh = hh0 + 32;
                float rg = sig_ap(gi[hh]      + ghA[hh]      + ghB[hh]);
                float zg = sig_ap(gi[40 + hh] + ghA[40 + hh] + ghB[40 + hh]);
                float hn = ghA[80 + hh] + ghB[80 + hh];
                float ng = tanh_ap(fmaf(rg, hn, gi[80 + hh]));
                float* hp = sm + K2_H + hh * HS2 + bq + cb;
                float ho = *hp;
                *hp = fmaf(zg, ho - ng, ng);
            }
        }
        asm volatile("bar.sync %0, 64;" :: "r"(barid) : "memory");
    }

    __syncthreads();
    if (tid < K2_BN) {
        float acc = bfc[c];
        #pragma unroll
        for (int h2 = 0; h2 < H_; ++h2)
            acc += sm[K2_H + h2 * HS2 + tid] * Wfc[c * H_ + h2];
        out[(size_t)(b0 + tid) * C_ + c] = sigf(acc);
    }
}

extern "C" void kernel_launch(void* const* d_in, const int* in_sizes, int n_in,
                              void* d_out, int out_size)
{
    const float* x   = (const float*)d_in[0];
    const float* Wih = (const float*)d_in[1];
    const float* Whh = (const float*)d_in[2];
    const float* bih = (const float*)d_in[3];
    const float* bhh = (const float*)d_in[4];
    const float* Wfc = (const float*)d_in[5];
    const float* bfc = (const float*)d_in[6];
    float* out = (float*)d_out;

    const int sm1 = K1_TOT * (int)sizeof(float);   // 65536
    const int sm2 = K2_TOT * (int)sizeof(float);   // 56448
    cudaFuncSetAttribute(gi_gemm_kernel,
                         cudaFuncAttributeMaxDynamicSharedMemorySize, sm1);
    cudaFuncSetAttribute(gru_rec_kernel,
                         cudaFuncAttributeMaxDynamicSharedMemorySize, sm2);

    gi_gemm_kernel<<<K1_GRID, 256, sm1>>>(x, Wih, bih);
    gru_rec_kernel<<<256, 256, sm2>>>(Whh, bhh, Wfc, bfc, out);
}

// round 17
// speedup vs baseline: 1.1187x; 1.0573x over previous
#include <cuda_runtime.h>
#include <math.h>

#define C_   16
#define I_   64
#define H_   40
#define T_   512
#define G_   120
#define GP   128

typedef unsigned long long u64;

// 1 GB scratch: gi[b][c][t][g], rows of 120 floats (b_ih folded in)
__device__ float g_gi[(size_t)256 * 16 * 512 * 120];

__device__ __forceinline__ u64 pack2(float lo, float hi) {
    u64 r;
    asm("mov.b64 %0, {%1, %2};"
        : "=l"(r) : "r"(__float_as_uint(lo)), "r"(__float_as_uint(hi)));
    return r;
}
__device__ __forceinline__ u64 dup2(float v) {
    u64 r;
    asm("mov.b64 %0, {%1, %1};" : "=l"(r) : "r"(__float_as_uint(v)));
    return r;
}
__device__ __forceinline__ u64 fma2(u64 a, u64 b, u64 c) {
    u64 d;
    asm("fma.rn.f32x2 %0, %1, %2, %3;" : "=l"(d) : "l"(a), "l"(b), "l"(c));
    return d;
}
__device__ __forceinline__ float lo32(u64 v) { return ((const float2*)&v)->x; }
__device__ __forceinline__ float hi32(u64 v) { return ((const float2*)&v)->y; }
__device__ __forceinline__ float tanh_ap(float x) {
    float r;
    asm("tanh.approx.f32 %0, %1;" : "=f"(r) : "f"(x));
    return r;
}
__device__ __forceinline__ float sig_ap(float v) {
    return fmaf(0.5f, tanh_ap(0.5f * v), 0.5f);
}
__device__ __forceinline__ float sigf(float v) {
    return __fdividef(1.0f, 1.0f + __expf(-v));
}

// ============================================================================
// Kernel 1: gi = W_ih . x + b_ih. Persistent grid 296, 256 thr, 2 CTAs/SM.
// Batch-pair packed accumulators: x pairs load pre-packed (no dup2);
// weights duplicated (4 dup2/k). 41 issues per 32 fma2.
// Lane owns gates 4*lane..4*lane+3; epilogue = coalesced STG.128.
// ============================================================================
#define K1_GRID 296
#define K1_NIT  4096                 // 16 c x 16 bblk x 16 tq
#define K1_BN   16
#define K1_TCH  8
#define K1_WIH  0                    // [64][128]
#define K1_X    (K1_WIH + I_ * GP)   // [8][64][16]
#define K1_TOT  (K1_X + K1_TCH * I_ * K1_BN)   // 16384 floats = 65536 B

__global__ void __launch_bounds__(256, 2)
gi_gemm_kernel(const float* __restrict__ x,
               const float* __restrict__ Wih,
               const float* __restrict__ bih)
{
    extern __shared__ float sm[];
    const int tid = threadIdx.x;
    const int bid = blockIdx.x;

    const int start = (K1_NIT * bid) / K1_GRID;
    const int end   = (K1_NIT * (bid + 1)) / K1_GRID;

    const int wid = tid >> 5;
    const int gt  = tid & 31;
    const int th  = tid & 1;
    const int lb  = (tid >> 1) & 15;
    const int lig = tid >> 5;

    const float* wI = sm + K1_WIH + 4 * gt;   // lane's 4 gates

    int c_cur = -1;
    u64 bI[4] = {0ull, 0ull, 0ull, 0ull};

    for (int it = start; it < end; ++it) {
        const int c  = it >> 8;
        const int rm = it & 255;
        const int b0 = (rm >> 4) * K1_BN;
        const int t0 = (rm & 15) * 32;

        if (c != c_cur) {
            __syncthreads();
            for (int p = tid; p < I_ * GP; p += 256) {
                int k = p >> 7, g = p & 127;
                sm[K1_WIH + p] = (g < G_) ? Wih[(c * G_ + g) * I_ + k] : 0.0f;
            }
            #pragma unroll
            for (int j = 0; j < 4; ++j) {
                int g = 4 * gt + j;
                bI[j] = (g < G_) ? dup2(bih[c * G_ + g]) : 0ull;
            }
            c_cur = c;
            __syncthreads();
        }

        const float* xg = x + ((size_t)(b0 + lb) * C_ + c) * (size_t)(I_ * T_);

        for (int tc = t0; tc < t0 + 32; tc += K1_TCH) {
            __syncthreads();
            #pragma unroll
            for (int r = 0; r < 8; ++r) {
                int i = lig + (r << 3);
                float4 v = *(const float4*)(xg + i * T_ + tc + 4 * th);
                float* xp = sm + K1_X + i * 16 + lb;    // tt stride = 1024
                xp[(4 * th + 0) * 1024] = v.x;
                xp[(4 * th + 1) * 1024] = v.y;
                xp[(4 * th + 2) * 1024] = v.z;
                xp[(4 * th + 3) * 1024] = v.w;
            }
            __syncthreads();

            // a[j][bp]: gate 4*gt+j, batch pair (2bp, 2bp+1)
            u64 a[4][8];
            #pragma unroll
            for (int j = 0; j < 4; ++j)
                #pragma unroll
                for (int bp = 0; bp < 8; ++bp) a[j][bp] = bI[j];

            const float* xr = sm + K1_X + wid * 1024;
            #pragma unroll 2
            for (int k = 0; k < I_; ++k) {
                float4 wv = *(const float4*)(wI + k * GP);
                u64 w0 = dup2(wv.x), w1 = dup2(wv.y);
                u64 w2 = dup2(wv.z), w3 = dup2(wv.w);
                const ulonglong2* xk = (const ulonglong2*)(xr + k * 16);
                ulonglong2 p0 = xk[0], p1 = xk[1], p2 = xk[2], p3 = xk[3];
                u64 xp[8] = {p0.x, p0.y, p1.x, p1.y, p2.x, p2.y, p3.x, p3.y};
                #pragma unroll
                for (int bp = 0; bp < 8; ++bp) {
                    a[0][bp] = fma2(w0, xp[bp], a[0][bp]);
                    a[1][bp] = fma2(w1, xp[bp], a[1][bp]);
                    a[2][bp] = fma2(w2, xp[bp], a[2][bp]);
                    a[3][bp] = fma2(w3, xp[bp], a[3][bp]);
                }
            }

            // epilogue: lane writes gates [4gt, 4gt+4) for each batch
            const int t = tc + wid;
            if (gt < 30) {
                #pragma unroll
                for (int bp = 0; bp < 8; ++bp) {
                    float* gpe = g_gi
                        + (((size_t)(b0 + 2 * bp) * C_ + c) * T_ + t) * G_ + 4 * gt;
                    float* gpo = gpe + (size_t)C_ * T_ * G_;
                    float4 vlo, vhi;
                    vlo.x = lo32(a[0][bp]); vlo.y = lo32(a[1][bp]);
                    vlo.z = lo32(a[2][bp]); vlo.w = lo32(a[3][bp]);
                    vhi.x = hi32(a[0][bp]); vhi.y = hi32(a[1][bp]);
                    vhi.z = hi32(a[2][bp]); vhi.w = hi32(a[3][bp]);
                    *(float4*)gpe = vlo;
                    *(float4*)gpo = vhi;
                }
            }
        }
    }
}

// ============================================================================
// Kernel 2: recurrence, k-split warp pairs + tanh.approx (R15, 642us).
// ============================================================================
#define K2_BN 16
#define HS2   20
#define PRS2  136
#define KH    20
#define K2_WST 0
#define K2_H   (K2_WST + H_ * GP)
#define K2_GH  (K2_H + H_ * HS2)
#define K2_GIB (K2_GH + 2 * K2_BN * PRS2)
#define K2_TOT (K2_GIB + 4 * 2 * 4 * G_)

__device__ __forceinline__ void cp16(unsigned smem_addr, const void* gptr) {
    asm volatile("cp.async.ca.shared.global [%0], [%1], 16;"
                 :: "r"(smem_addr), "l"(gptr));
}

__global__ void __launch_bounds__(256, 2)
gru_rec_kernel(const float* __restrict__ Whh,
               const float* __restrict__ bhh,
               const float* __restrict__ Wfc,
               const float* __restrict__ bfc,
               float* __restrict__ out)
{
    extern __shared__ float sm[];
    const int tid = threadIdx.x;
    const int c   = blockIdx.x & 15;
    const int b0  = (blockIdx.x >> 4) * K2_BN;

    for (int p = tid; p < H_ * GP; p += 256) {
        int k = p >> 7, g = p & 127;
        sm[K2_WST + p] = (g < G_) ? Whh[(c * G_ + g) * H_ + k] : 0.0f;
    }
    for (int p = tid; p < H_ * HS2; p += 256) sm[K2_H + p] = 0.0f;
    __syncthreads();

    const int wid  = tid >> 5;
    const int gt   = tid & 31;
    const int pair = wid >> 1;
    const int half = wid & 1;
    const int bq   = pair * 4;
    const int barid = 1 + pair;

    u64 w0r[KH], w1r[KH];
    #pragma unroll
    for (int kk = 0; kk < KH; ++kk) {
        int k = half * KH + kk;
        w0r[kk] = *(const u64*)(sm + K2_WST + k * GP + 2 * gt);
        w1r[kk] = *(const u64*)(sm + K2_WST + k * GP + 64 + 2 * gt);
    }

    const int g0 = 2 * gt, g1 = 64 + 2 * gt;
    u64 bH0 = 0ull, bH1 = 0ull;
    if (half == 0) {
        float b1a = (g1     < G_) ? bhh[c * G_ + g1]     : 0.0f;
        float b1b = (g1 + 1 < G_) ? bhh[c * G_ + g1 + 1] : 0.0f;
        bH0 = pack2(bhh[c * G_ + g0], bhh[c * G_ + g0 + 1]);
        bH1 = pack2(b1a, b1b);
    }

    const int mb = bq + 2 * half;
    const unsigned gib_pair =
        (unsigned)__cvta_generic_to_shared(sm + K2_GIB + pair * 960);
    const int ch0 = gt,      b_of0 = ch0 / 30, o_of0 = ch0 % 30;
    const int ch1 = gt + 32, b_of1 = ch1 / 30, o_of1 = ch1 % 30;
    const size_t r0 = ((size_t)(b0 + mb + b_of0) * C_ + c) * T_;
    const size_t r1 = ((size_t)(b0 + mb + b_of1) * C_ + c) * T_;
    const unsigned d0off = (unsigned)((2 * half + b_of0) * G_ + o_of0 * 4) * 4u;
    const unsigned d1off = (unsigned)((2 * half + b_of1) * G_ + o_of1 * 4) * 4u;

    cp16(gib_pair + d0off, g_gi + r0 * G_ + (size_t)o_of0 * 4);
    if (ch1 < 60)
        cp16(gib_pair + d1off, g_gi + r1 * G_ + (size_t)o_of1 * 4);
    asm volatile("cp.async.commit_group;");

    const int lp  = half * 32 + gt;
    const int cb  = lp & 3;
    const int hh0 = lp >> 2;

    const float* ghA = sm + K2_GH + (bq + cb) * PRS2;
    const float* ghB = ghA + K2_BN * PRS2;
    float* myGH = sm + K2_GH + half * (K2_BN * PRS2);

    for (int t = 0; t < T_; ++t) {
        if (t + 1 < T_) {
            unsigned dst = gib_pair + (unsigned)(((t + 1) & 1) * 480) * 4u;
            cp16(dst + d0off, g_gi + (r0 + t + 1) * G_ + (size_t)o_of0 * 4);
            if (ch1 < 60)
                cp16(dst + d1off, g_gi + (r1 + t + 1) * G_ + (size_t)o_of1 * 4);
        }
        asm volatile("cp.async.commit_group;");
        asm volatile("cp.async.wait_group 1;");

        u64 a0[4], a1[4];
        a0[0] = bH0; a0[1] = bH0; a0[2] = bH0; a0[3] = bH0;
        a1[0] = bH1; a1[1] = bH1; a1[2] = bH1; a1[3] = bH1;
        const float* hrow = sm + K2_H + half * KH * HS2 + bq;
        #pragma unroll
        for (int kk = 0; kk < KH; ++kk) {
            float4 hv = *(const float4*)(hrow + kk * HS2);
            u64 d0 = dup2(hv.x), d1 = dup2(hv.y), d2 = dup2(hv.z), d3 = dup2(hv.w);
            a0[0] = fma2(w0r[kk], d0, a0[0]); a1[0] = fma2(w1r[kk], d0, a1[0]);
            a0[1] = fma2(w0r[kk], d1, a0[1]); a1[1] = fma2(w1r[kk], d1, a1[1]);
            a0[2] = fma2(w0r[kk], d2, a0[2]); a1[2] = fma2(w1r[kk], d2, a1[2]);
            a0[3] = fma2(w0r[kk], d3, a0[3]); a1[3] = fma2(w1r[kk], d3, a1[3]);
        }
        #pragma unroll
        for (int b = 0; b < 4; ++b) {
            float* pg = myGH + (bq + b) * PRS2 + 2 * gt;
            *(u64*)pg        = a0[b];
            *(u64*)(pg + 64) = a1[b];
        }
        asm volatile("bar.sync %0, 64;" :: "r"(barid) : "memory");

        {
            const float* gi = sm + K2_GIB + pair * 960 + (t & 1) * 480 + cb * G_;
            #pragma unroll
            for (int q = 0; q < 2; ++q) {
                int hh = hh0 + 16 * q;
                float rg = sig_ap(gi[hh]      + ghA[hh]      + ghB[hh]);
                float zg = sig_ap(gi[40 + hh] + ghA[40 + hh] + ghB[40 + hh]);
                float hn = ghA[80 + hh] + ghB[80 + hh];
                float ng = tanh_ap(fmaf(rg, hn, gi[80 + hh]));
                float* hp = sm + K2_H + hh * HS2 + bq + cb;
                float ho = *hp;
                *hp = fmaf(zg, ho - ng, ng);
            }
            if (lp < 32) {
                int hh = hh0 + 32;
                float rg = sig_ap(gi[hh]      + ghA[hh]      + ghB[hh]);
                float zg = sig_ap(gi[40 + hh] + ghA[40 + hh] + ghB[40 + hh]);
                float hn = ghA[80 + hh] + ghB[80 + hh];
                float ng = tanh_ap(fmaf(rg, hn, gi[80 + hh]));
                float* hp = sm + K2_H + hh * HS2 + bq + cb;
                float ho = *hp;
                *hp = fmaf(zg, ho - ng, ng);
            }
        }
        asm volatile("bar.sync %0, 64;" :: "r"(barid) : "memory");
    }

    __syncthreads();
    if (tid < K2_BN) {
        float acc = bfc[c];
        #pragma unroll
        for (int h2 = 0; h2 < H_; ++h2)
            acc += sm[K2_H + h2 * HS2 + tid] * Wfc[c * H_ + h2];
        out[(size_t)(b0 + tid) * C_ + c] = sigf(acc);
    }
}

extern "C" void kernel_launch(void* const* d_in, const int* in_sizes, int n_in,
                              void* d_out, int out_size)
{
    const float* x   = (const float*)d_in[0];
    const float* Wih = (const float*)d_in[1];
    const float* Whh = (const float*)d_in[2];
    const float* bih = (const float*)d_in[3];
    const float* bhh = (const float*)d_in[4];
    const float* Wfc = (const float*)d_in[5];
    const float* bfc = (const float*)d_in[6];
    float* out = (float*)d_out;

    const int sm1 = K1_TOT * (int)sizeof(float);   // 65536
    const int sm2 = K2_TOT * (int)sizeof(float);   // 56448
    cudaFuncSetAttribute(gi_gemm_kernel,
                         cudaFuncAttributeMaxDynamicSharedMemorySize, sm1);
    cudaFuncSetAttribute(gru_rec_kernel,
                         cudaFuncAttributeMaxDynamicSharedMemorySize, sm2);

    gi_gemm_kernel<<<K1_GRID, 256, sm1>>>(x, Wih, bih);
    gru_rec_kernel<<<256, 256, sm2>>>(Whh, bhh, Wfc, bfc, out);
}